// round 6
// baseline (speedup 1.0000x reference)
#include <cuda_runtime.h>

// Fixed shapes: B=8, S=4096, D=1024, H=12
#define SS 4096
#define ROWS_PER_BLOCK 8
#define F4_PER_ROW 256   // D/4

#define X_TOTAL_BYTES 134217728u   // 8*4096*1024*4
#define X_PIN_BYTES   100663296u   // 96 MB pinned evict_last (< 126 MB L2)

// Range policy: x[0 .. 96MB) -> evict_last (persists across graph replays),
// x[96MB .. 134MB) -> evict_first (streams). Stores use .cs so the output
// never displaces the pinned read set.
__device__ __forceinline__ float4 ld_hint(const float4* p, unsigned long long pol) {
    float4 v;
    asm volatile("ld.global.nc.L2::cache_hint.v4.f32 {%0,%1,%2,%3}, [%4], %5;"
                 : "=f"(v.x), "=f"(v.y), "=f"(v.z), "=f"(v.w)
                 : "l"(p), "l"(pol));
    return v;
}

__global__ void __launch_bounds__(256) fused_resonance_kernel(
    const float4* __restrict__ x,
    float4* __restrict__ out,
    const float* __restrict__ freqs,
    const float* __restrict__ amps,
    const float* __restrict__ time_p)
{
    __shared__ float s_w[ROWS_PER_BLOCK];

    const unsigned int tid  = threadIdx.x;
    const unsigned int row0 = blockIdx.x * ROWS_PER_BLOCK;
    const unsigned int base = row0 * F4_PER_ROW + tid;

    // Address-range policy anchored at x: deterministic pinned subset.
    unsigned long long pol;
    asm volatile("createpolicy.range.L2::evict_last.L2::evict_first.b64 %0, [%1], %2, %3;"
                 : "=l"(pol)
                 : "l"(x), "r"(X_PIN_BYTES), "r"(X_TOTAL_BYTES));

    // Front-batch 8 independent loads (MLP_p1 = 8)
    float4 v[ROWS_PER_BLOCK];
    #pragma unroll
    for (int j = 0; j < ROWS_PER_BLOCK; j++) {
        v[j] = ld_hint(&x[base + j * F4_PER_ROW], pol);
    }

    // Overlapped with loads: 8 threads compute wave[s] for this block's rows.
    // Exact fp32 op order of the reference:
    //   c_i = (2*pi)*f_i (fp32 round); phase = c_i*(time + s/S); sum/12
    if (tid < ROWS_PER_BLOCK) {
        const unsigned int s = (row0 + tid) & (SS - 1);
        const float arg = *time_p + (float)s / (float)SS;
        float acc = 0.0f;
        #pragma unroll
        for (int i = 0; i < 12; i++) {
            float c = 6.283185307179586f * freqs[i];
            acc += amps[i] * sinf(c * arg);
        }
        s_w[tid] = acc / 12.0f;
    }
    __syncthreads();

    #pragma unroll
    for (int j = 0; j < ROWS_PER_BLOCK; j++) {
        const float w = s_w[j];
        float4 r = v[j];
        r.x *= w; r.y *= w; r.z *= w; r.w *= w;
        __stcs(&out[base + j * F4_PER_ROW], r);   // evict_first stream
    }
}

extern "C" void kernel_launch(void* const* d_in, const int* in_sizes, int n_in,
                              void* d_out, int out_size) {
    const float* x     = (const float*)d_in[0];
    const float* freqs = (const float*)d_in[1];
    const float* amps  = (const float*)d_in[2];
    const float* timep = (const float*)d_in[3];
    float* out = (float*)d_out;

    // total rows = B*S = 32768; 8 rows per block -> 4096 blocks
    fused_resonance_kernel<<<4096, 256>>>(
        (const float4*)x, (float4*)out, freqs, amps, timep);
}

// round 7
// speedup vs baseline: 1.0404x; 1.0404x over previous
#include <cuda_runtime.h>
#include <cstdint>

// Fixed shapes: B=8, S=4096, D=1024, H=12
#define SS 4096
#define ROWS_PER_BLOCK 16
#define F8_PER_ROW 128          // D/8 : 32-byte units per row

struct F8 { uint4 a, b; };

__device__ __forceinline__ F8 ld_v8(const F8* p) {
    F8 v;
    asm volatile("ld.global.nc.v8.b32 {%0,%1,%2,%3,%4,%5,%6,%7}, [%8];"
                 : "=r"(v.a.x), "=r"(v.a.y), "=r"(v.a.z), "=r"(v.a.w),
                   "=r"(v.b.x), "=r"(v.b.y), "=r"(v.b.z), "=r"(v.b.w)
                 : "l"(p));
    return v;
}
__device__ __forceinline__ void st_v8(F8* p, const F8& v) {
    asm volatile("st.global.v8.b32 [%0], {%1,%2,%3,%4,%5,%6,%7,%8};"
                 :: "l"(p),
                    "r"(v.a.x), "r"(v.a.y), "r"(v.a.z), "r"(v.a.w),
                    "r"(v.b.x), "r"(v.b.y), "r"(v.b.z), "r"(v.b.w)
                 : "memory");
}
__device__ __forceinline__ uint32_t mulf(uint32_t u, float w) {
    return __float_as_uint(__uint_as_float(u) * w);
}
__device__ __forceinline__ F8 scale8(F8 v, float w) {
    v.a.x = mulf(v.a.x, w); v.a.y = mulf(v.a.y, w);
    v.a.z = mulf(v.a.z, w); v.a.w = mulf(v.a.w, w);
    v.b.x = mulf(v.b.x, w); v.b.y = mulf(v.b.y, w);
    v.b.z = mulf(v.b.z, w); v.b.w = mulf(v.b.w, w);
    return v;
}

// One block = 16 contiguous rows (16*1024 floats = 2048 x 32B units).
// Each thread moves 8 x 32B = 256B in two front-batched batches of 4.
// 32B-unit u = j*256 + tid (j=0..7); its row within block = u >> 7.
__global__ void __launch_bounds__(256) fused_resonance_kernel(
    const F8* __restrict__ x,
    F8* __restrict__ out,
    const float* __restrict__ freqs,
    const float* __restrict__ amps,
    const float* __restrict__ time_p)
{
    __shared__ float s_w[ROWS_PER_BLOCK];

    const unsigned int tid  = threadIdx.x;
    const unsigned int row0 = blockIdx.x * ROWS_PER_BLOCK;
    const unsigned int base = row0 * F8_PER_ROW + tid;   // in 32B units
    const unsigned int rsub = tid >> 7;                  // 0 or 1

    // ---- batch 1: rows 0..7 of this block (front-batched, MLP=4x32B) ----
    F8 v[4];
    #pragma unroll
    for (int j = 0; j < 4; j++) v[j] = ld_v8(&x[base + j * 256]);

    // Overlapped with loads: 16 threads compute wave[s] for this block's rows.
    // Exact fp32 op order of the reference:
    //   c_i = (2*pi)*f_i (fp32 round); phase = c_i*(time + s/S); sum/12
    if (tid < ROWS_PER_BLOCK) {
        const unsigned int s = (row0 + tid) & (SS - 1);
        const float arg = *time_p + (float)s / (float)SS;
        float acc = 0.0f;
        #pragma unroll
        for (int i = 0; i < 12; i++) {
            float c = 6.283185307179586f * freqs[i];
            acc += amps[i] * sinf(c * arg);
        }
        s_w[tid] = acc / 12.0f;
    }
    __syncthreads();

    #pragma unroll
    for (int j = 0; j < 4; j++) {
        const float w = s_w[2 * j + rsub];
        st_v8(&out[base + j * 256], scale8(v[j], w));
    }

    // ---- batch 2: rows 8..15 ----
    #pragma unroll
    for (int j = 0; j < 4; j++) v[j] = ld_v8(&x[base + 1024 + j * 256]);
    #pragma unroll
    for (int j = 0; j < 4; j++) {
        const float w = s_w[8 + 2 * j + rsub];
        st_v8(&out[base + 1024 + j * 256], scale8(v[j], w));
    }
}

extern "C" void kernel_launch(void* const* d_in, const int* in_sizes, int n_in,
                              void* d_out, int out_size) {
    const float* x     = (const float*)d_in[0];
    const float* freqs = (const float*)d_in[1];
    const float* amps  = (const float*)d_in[2];
    const float* timep = (const float*)d_in[3];
    float* out = (float*)d_out;

    // total rows = B*S = 32768; 16 rows per block -> 2048 blocks
    fused_resonance_kernel<<<2048, 256>>>(
        (const F8*)x, (F8*)out, freqs, amps, timep);
}